// round 1
// baseline (speedup 1.0000x reference)
#include <cuda_runtime.h>
#include <cuda_bf16.h>

// ---------------- problem constants ----------------
#define BB 4
#define LL 2048
#define DD 2048
#define SS 16
#define KK 4
#define NB 2
#define HH 32
#define HD 64
#define EPSF 1e-6f

// ---------------- device scratch (no allocs allowed) ----------------
__device__ float g_x[BB * LL * DD];        // current x (mutated across rounds)
__device__ float g_q[BB * LL * DD];        // q projection
__device__ float g_xb[BB * LL * DD];       // attention output branch
__device__ float g_att[BB * LL * HH * SS]; // att, layout (b, l, h*16+s)
__device__ float g_voT[BB * DD * HH * SS]; // folded V*out_proj, layout (b, d, h*16+s)
__device__ float g_logits[BB * LL * SS];
__device__ float g_ws[BB * SS * DD];
__device__ float g_kv[BB * SS * 2 * DD];   // [kk | vv]
__device__ float g_xg[BB * SS * KK * DD];  // gathered x rows
__device__ float g_wxg[BB * SS * KK * DD]; // write-proj of gathered rows
__device__ float g_wgt[BB * SS * KK];
__device__ int   g_idx[BB * SS * KK];

// ---------------- utility kernels ----------------
__global__ void copy4_kernel(const float* __restrict__ src, float* __restrict__ dst, int n4) {
    int i = blockIdx.x * blockDim.x + threadIdx.x;
    if (i < n4) ((float4*)dst)[i] = ((const float4*)src)[i];
}

__global__ void init_ws_kernel(const float* __restrict__ wsrc, float* __restrict__ ws) {
    int bs = blockIdx.x;            // b*S + s
    int s = bs % SS;
    for (int d = threadIdx.x; d < DD; d += blockDim.x)
        ws[(long)bs * DD + d] = wsrc[(long)s * DD + d];
}

// ---------------- compete logits: logits = rms(x)*npw @ cw.T + cb ----------------
// one warp per token; fuse rms (scale applied after dot since rms is row-scalar * elemwise w)
__global__ void compete_kernel(const float* __restrict__ x, const float* __restrict__ cw,
                               const float* __restrict__ cb, const float* __restrict__ npw,
                               float* __restrict__ logits) {
    int warp = threadIdx.x >> 5, lane = threadIdx.x & 31;
    int row = blockIdx.x * 8 + warp;           // < B*L
    const float* xr = x + (long)row * DD;
    float ss = 0.f;
    float acc[SS];
#pragma unroll
    for (int s = 0; s < SS; s++) acc[s] = 0.f;
    for (int j = lane; j < DD; j += 32) {
        float xv = xr[j];
        ss += xv * xv;
        float xn = xv * npw[j];
#pragma unroll
        for (int s = 0; s < SS; s++) acc[s] += xn * cw[s * DD + j];
    }
#pragma unroll
    for (int o = 16; o; o >>= 1) ss += __shfl_xor_sync(0xffffffffu, ss, o);
#pragma unroll
    for (int s = 0; s < SS; s++) {
#pragma unroll
        for (int o = 16; o; o >>= 1) acc[s] += __shfl_xor_sync(0xffffffffu, acc[s], o);
    }
    float rinv = rsqrtf(ss * (1.f / DD) + EPSF);
    float myv = 0.f;
#pragma unroll
    for (int s = 0; s < SS; s++) if (lane == s) myv = acc[s];
    if (lane < SS) logits[(long)row * SS + lane] = myv * rinv + cb[lane];
}

// ---------------- top-4 over L per (b,s) + softmax weights ----------------
__device__ __forceinline__ bool tk_better(float v1, int i1, float v2, int i2) {
    return (v1 > v2) || (v1 == v2 && i1 < i2);
}

__global__ void topk_kernel(const float* __restrict__ logits, int* __restrict__ idxo,
                            float* __restrict__ wgto) {
    int bs = blockIdx.x;               // b*S + s
    int b = bs / SS, s = bs % SS;
    float v[KK]; int id[KK];
#pragma unroll
    for (int k = 0; k < KK; k++) { v[k] = -3.4e38f; id[k] = 0x7fffffff; }
    for (int l = threadIdx.x; l < LL; l += 256) {
        float val = logits[((long)b * LL + l) * SS + s];
        if (tk_better(val, l, v[KK - 1], id[KK - 1])) {
            v[KK - 1] = val; id[KK - 1] = l;
#pragma unroll
            for (int j = KK - 1; j > 0; j--) {
                if (tk_better(v[j], id[j], v[j - 1], id[j - 1])) {
                    float tv = v[j]; v[j] = v[j - 1]; v[j - 1] = tv;
                    int ti = id[j]; id[j] = id[j - 1]; id[j - 1] = ti;
                }
            }
        }
    }
    __shared__ float sv[256 * KK];
    __shared__ int   si[256 * KK];
#pragma unroll
    for (int k = 0; k < KK; k++) { sv[threadIdx.x * KK + k] = v[k]; si[threadIdx.x * KK + k] = id[k]; }
    __syncthreads();
    if (threadIdx.x == 0) {
        float bv[KK]; int bi[KK];
#pragma unroll
        for (int k = 0; k < KK; k++) { bv[k] = -3.4e38f; bi[k] = 0x7fffffff; }
        for (int c = 0; c < 256 * KK; c++) {
            float val = sv[c]; int l = si[c];
            if (tk_better(val, l, bv[KK - 1], bi[KK - 1])) {
                bv[KK - 1] = val; bi[KK - 1] = l;
#pragma unroll
                for (int j = KK - 1; j > 0; j--) {
                    if (tk_better(bv[j], bi[j], bv[j - 1], bi[j - 1])) {
                        float tv = bv[j]; bv[j] = bv[j - 1]; bv[j - 1] = tv;
                        int ti = bi[j]; bi[j] = bi[j - 1]; bi[j - 1] = ti;
                    }
                }
            }
        }
        float m = bv[0];
        float e[KK]; float sum = 0.f;
#pragma unroll
        for (int k = 0; k < KK; k++) { e[k] = expf(bv[k] - m); sum += e[k]; }
        float inv = 1.f / sum;
#pragma unroll
        for (int k = 0; k < KK; k++) { wgto[bs * KK + k] = e[k] * inv; idxo[bs * KK + k] = bi[k]; }
    }
}

// ---------------- gather selected x rows ----------------
__global__ void gather_kernel(const float* __restrict__ x, const int* __restrict__ idx,
                              float* __restrict__ xg) {
    int r = blockIdx.x;                // (b*S+s)*K + k, 0..255
    int b = r / (SS * KK);
    int l = idx[r];
    const float* src = x + ((long)b * LL + l) * DD;
    float* dst = xg + (long)r * DD;
    for (int d = threadIdx.x; d < DD; d += blockDim.x) dst[d] = src[d];
}

// ---------------- generic fp32 SGEMM: C = A(M,K) @ W(N,K)^T + bias ----------------
// 128x128 tile, BK=8, 256 threads, 8x8 per-thread microtile. Batched via blockIdx.z.
__global__ __launch_bounds__(256) void sgemm_bias_kernel(
    const float* __restrict__ A, const float* __restrict__ W,
    const float* __restrict__ bias, float* __restrict__ C,
    int M, int N, int K, long strA, long strW, long strC) {
    A += (long)blockIdx.z * strA;
    W += (long)blockIdx.z * strW;
    C += (long)blockIdx.z * strC;

    __shared__ float As[8][128];
    __shared__ float Bs[8][128];

    const int tid = threadIdx.x;
    const int m0 = blockIdx.y * 128;
    const int n0 = blockIdx.x * 128;

    const int lrow = tid >> 1;            // 0..127
    const int lcol = (tid & 1) << 2;      // 0 or 4

    const int tx = tid & 15;
    const int ty = tid >> 4;

    float acc[8][8];
#pragma unroll
    for (int i = 0; i < 8; i++)
#pragma unroll
        for (int j = 0; j < 8; j++) acc[i][j] = 0.f;

    for (int k0 = 0; k0 < K; k0 += 8) {
        float4 av = make_float4(0.f, 0.f, 0.f, 0.f);
        float4 wv = make_float4(0.f, 0.f, 0.f, 0.f);
        if (m0 + lrow < M) av = *(const float4*)(A + (long)(m0 + lrow) * K + k0 + lcol);
        if (n0 + lrow < N) wv = *(const float4*)(W + (long)(n0 + lrow) * K + k0 + lcol);
        As[lcol + 0][lrow] = av.x; As[lcol + 1][lrow] = av.y;
        As[lcol + 2][lrow] = av.z; As[lcol + 3][lrow] = av.w;
        Bs[lcol + 0][lrow] = wv.x; Bs[lcol + 1][lrow] = wv.y;
        Bs[lcol + 2][lrow] = wv.z; Bs[lcol + 3][lrow] = wv.w;
        __syncthreads();
#pragma unroll
        for (int k = 0; k < 8; k++) {
            float a[8], bfr[8];
#pragma unroll
            for (int i = 0; i < 4; i++) { a[i] = As[k][ty * 4 + i]; a[4 + i] = As[k][64 + ty * 4 + i]; }
#pragma unroll
            for (int j = 0; j < 4; j++) { bfr[j] = Bs[k][tx * 4 + j]; bfr[4 + j] = Bs[k][64 + tx * 4 + j]; }
#pragma unroll
            for (int i = 0; i < 8; i++)
#pragma unroll
                for (int j = 0; j < 8; j++) acc[i][j] = fmaf(a[i], bfr[j], acc[i][j]);
        }
        __syncthreads();
    }
#pragma unroll
    for (int i = 0; i < 8; i++) {
        int m = m0 + ((i < 4) ? (ty * 4 + i) : (64 + ty * 4 + (i - 4)));
        if (m >= M) continue;
#pragma unroll
        for (int j = 0; j < 8; j++) {
            int n = n0 + ((j < 4) ? (tx * 4 + j) : (64 + tx * 4 + (j - 4)));
            if (n < N) C[(long)m * N + n] = acc[i][j] + bias[n];
        }
    }
}

// ---------------- ws = rms(ws + sum_k wgt*wxg_row, norm_post_w) ----------------
__global__ void ws_update_kernel(const float* __restrict__ wxg, const float* __restrict__ wgt,
                                 const float* __restrict__ npw, float* __restrict__ ws) {
    int bs = blockIdx.x;
    __shared__ float t[DD];
    __shared__ float red[256];
    float w0 = wgt[bs * KK + 0], w1 = wgt[bs * KK + 1];
    float w2 = wgt[bs * KK + 2], w3 = wgt[bs * KK + 3];
    const float* r0 = wxg + (long)(bs * KK + 0) * DD;
    const float* r1 = wxg + (long)(bs * KK + 1) * DD;
    const float* r2 = wxg + (long)(bs * KK + 2) * DD;
    const float* r3 = wxg + (long)(bs * KK + 3) * DD;
    float ssp = 0.f;
    for (int d = threadIdx.x; d < DD; d += 256) {
        float v = ws[(long)bs * DD + d] + w0 * r0[d] + w1 * r1[d] + w2 * r2[d] + w3 * r3[d];
        t[d] = v; ssp += v * v;
    }
    red[threadIdx.x] = ssp; __syncthreads();
    for (int st = 128; st; st >>= 1) {
        if (threadIdx.x < st) red[threadIdx.x] += red[threadIdx.x + st];
        __syncthreads();
    }
    float rinv = rsqrtf(red[0] * (1.f / DD) + EPSF);
    for (int d = threadIdx.x; d < DD; d += 256)
        ws[(long)bs * DD + d] = t[d] * rinv * npw[d];
}

// ---------------- fold vv with out_proj: voT[b,d,h*16+s] = sum_i vv[b,s,h,i]*Wout[d,h*64+i] ----------------
__global__ __launch_bounds__(128) void vo_kernel(const float* __restrict__ kv,
                                                 const float* __restrict__ wout,
                                                 float* __restrict__ voT) {
    int b = blockIdx.y / HH, h = blockIdx.y % HH;
    int d0 = blockIdx.x * 128;
    __shared__ float vs[SS][HD];
    __shared__ float wsm[128][HD + 1];
    for (int e = threadIdx.x; e < SS * HD; e += 128) {
        int s = e >> 6, i = e & 63;
        vs[s][i] = kv[((long)b * SS + s) * (2 * DD) + DD + h * HD + i];
    }
    for (int e = threadIdx.x; e < 128 * HD; e += 128) {
        int r = e >> 6, i = e & 63;
        wsm[r][i] = wout[(long)(d0 + r) * DD + h * HD + i];
    }
    __syncthreads();
    int d = threadIdx.x;
    float acc[SS];
#pragma unroll
    for (int s = 0; s < SS; s++) acc[s] = 0.f;
#pragma unroll
    for (int i = 0; i < HD; i++) {
        float w = wsm[d][i];
#pragma unroll
        for (int s = 0; s < SS; s++) acc[s] += w * vs[s][i];
    }
    float* out = voT + ((long)b * DD + d0 + d) * (HH * SS) + h * SS;
#pragma unroll
    for (int s = 0; s < SS; s++) out[s] = acc[s];
}

// ---------------- att[b,l,h*16+s] = softmax_s(q.k * 0.125) ----------------
__global__ __launch_bounds__(256) void att_kernel(const float* __restrict__ q,
                                                  const float* __restrict__ kv,
                                                  float* __restrict__ att) {
    int b = blockIdx.y / HH, h = blockIdx.y % HH;
    int l0 = blockIdx.x * 64;
    __shared__ float ks[SS][HD];
    __shared__ float qs[64][HD + 1];
    __shared__ float sc[64][SS + 1];
    for (int e = threadIdx.x; e < SS * HD; e += 256) {
        int s = e >> 6, i = e & 63;
        ks[s][i] = kv[((long)b * SS + s) * (2 * DD) + h * HD + i];
    }
    for (int e = threadIdx.x; e < 64 * HD; e += 256) {
        int r = e >> 6, i = e & 63;
        qs[r][i] = q[((long)b * LL + l0 + r) * DD + h * HD + i];
    }
    __syncthreads();
    int r = threadIdx.x & 63, sg = threadIdx.x >> 6;
#pragma unroll
    for (int j = 0; j < 4; j++) {
        int s = sg * 4 + j;
        float a = 0.f;
#pragma unroll
        for (int i = 0; i < HD; i++) a += qs[r][i] * ks[s][i];
        sc[r][s] = a * 0.125f;
    }
    __syncthreads();
    if (threadIdx.x < 64) {
        int rr = threadIdx.x;
        float m = sc[rr][0];
#pragma unroll
        for (int s = 1; s < SS; s++) m = fmaxf(m, sc[rr][s]);
        float e[SS]; float sum = 0.f;
#pragma unroll
        for (int s = 0; s < SS; s++) { e[s] = expf(sc[rr][s] - m); sum += e[s]; }
        float inv = 1.f / sum;
        float* o = att + ((long)b * LL + l0 + rr) * (HH * SS) + h * SS;
#pragma unroll
        for (int s = 0; s < SS; s++) o[s] = e[s] * inv;
    }
}

// ---------------- x_out = rms(x + xb, norm_post_w) ----------------
__global__ void resid_rms_kernel(const float* __restrict__ xin, const float* __restrict__ xb,
                                 const float* __restrict__ npw, float* __restrict__ xout) {
    long row = blockIdx.x;
    __shared__ float t[DD];
    __shared__ float red[256];
    const float* a = xin + row * DD;
    const float* c = xb + row * DD;
    float ssp = 0.f;
    for (int d = threadIdx.x; d < DD; d += 256) {
        float v = a[d] + c[d];
        t[d] = v; ssp += v * v;
    }
    red[threadIdx.x] = ssp; __syncthreads();
    for (int st = 128; st; st >>= 1) {
        if (threadIdx.x < st) red[threadIdx.x] += red[threadIdx.x + st];
        __syncthreads();
    }
    float rinv = rsqrtf(red[0] * (1.f / DD) + EPSF);
    for (int d = threadIdx.x; d < DD; d += 256)
        xout[row * DD + d] = t[d] * rinv * npw[d];
}

// ---------------- host launch ----------------
extern "C" void kernel_launch(void* const* d_in, const int* in_sizes, int n_in,
                              void* d_out, int out_size) {
    const float* x_in       = (const float*)d_in[0];
    const float* workspace  = (const float*)d_in[1];
    const float* compete_w  = (const float*)d_in[2];
    const float* compete_b  = (const float*)d_in[3];
    const float* write_w    = (const float*)d_in[4];
    const float* write_b    = (const float*)d_in[5];
    const float* in_proj_w  = (const float*)d_in[6];
    const float* in_proj_b  = (const float*)d_in[7];
    const float* out_proj_w = (const float*)d_in[8];
    const float* out_proj_b = (const float*)d_in[9];
    // d_in[10], d_in[11] = ig_w, ig_b : dead code in reference, unused
    const float* norm_pre_w  = (const float*)d_in[12];
    const float* norm_post_w = (const float*)d_in[13];

    void *px_, *pq_, *pxb_, *patt_, *pvoT_, *plog_, *pws_, *pkv_, *pxg_, *pwxg_, *pwgt_, *pidx_;
    cudaGetSymbolAddress(&px_, g_x);
    cudaGetSymbolAddress(&pq_, g_q);
    cudaGetSymbolAddress(&pxb_, g_xb);
    cudaGetSymbolAddress(&patt_, g_att);
    cudaGetSymbolAddress(&pvoT_, g_voT);
    cudaGetSymbolAddress(&plog_, g_logits);
    cudaGetSymbolAddress(&pws_, g_ws);
    cudaGetSymbolAddress(&pkv_, g_kv);
    cudaGetSymbolAddress(&pxg_, g_xg);
    cudaGetSymbolAddress(&pwxg_, g_wxg);
    cudaGetSymbolAddress(&pwgt_, g_wgt);
    cudaGetSymbolAddress(&pidx_, g_idx);
    float* px   = (float*)px_;
    float* pq   = (float*)pq_;
    float* pxb  = (float*)pxb_;
    float* patt = (float*)patt_;
    float* pvoT = (float*)pvoT_;
    float* plog = (float*)plog_;
    float* pws  = (float*)pws_;
    float* pkv  = (float*)pkv_;
    float* pxg  = (float*)pxg_;
    float* pwxg = (float*)pwxg_;
    float* pwgt = (float*)pwgt_;
    int*   pidx = (int*)pidx_;

    // init: x <- input, ws <- broadcast(workspace)
    {
        int n4 = BB * LL * DD / 4;
        copy4_kernel<<<(n4 + 255) / 256, 256>>>(x_in, px, n4);
        init_ws_kernel<<<BB * SS, 256>>>(workspace, pws);
    }

    for (int it = 0; it < NB; it++) {
        // 1. compete logits
        compete_kernel<<<BB * LL / 8, 256>>>(px, compete_w, compete_b, norm_pre_w, plog);
        // 2. top-k + softmax weights
        topk_kernel<<<BB * SS, 256>>>(plog, pidx, pwgt);
        // 3. gather selected rows
        gather_kernel<<<BB * SS * KK, 256>>>(px, pidx, pxg);
        // 4. write projection of gathered rows: (256, D) @ write_w^T
        {
            dim3 grid(DD / 128, (BB * SS * KK + 127) / 128, 1);
            sgemm_bias_kernel<<<grid, 256>>>(pxg, write_w, write_b, pwxg,
                                             BB * SS * KK, DD, DD, 0, 0, 0);
        }
        // 5. workspace update + rms
        ws_update_kernel<<<BB * SS, 256>>>(pwxg, pwgt, norm_post_w, pws);
        // 6. kk|vv projection: (64, D) @ [wk;wv]^T -> (64, 2D)
        {
            dim3 grid((2 * DD) / 128, 1, 1);
            sgemm_bias_kernel<<<grid, 256>>>(pws, in_proj_w + (long)DD * DD, in_proj_b + DD,
                                             pkv, BB * SS, 2 * DD, DD, 0, 0, 0);
        }
        // 7. q projection: (B*L, D) @ wq^T  [the big one]
        {
            dim3 grid(DD / 128, BB * LL / 128, 1);
            sgemm_bias_kernel<<<grid, 256>>>(px, in_proj_w, in_proj_b, pq,
                                             BB * LL, DD, DD, 0, 0, 0);
        }
        // 8. fold vv with out_proj
        {
            dim3 grid(DD / 128, BB * HH, 1);
            vo_kernel<<<grid, 128>>>(pkv, out_proj_w, pvoT);
        }
        // 9. attention scores + softmax
        {
            dim3 grid(LL / 64, BB * HH, 1);
            att_kernel<<<grid, 256>>>(pq, pkv, patt);
        }
        // 10. x_b = att @ voT^T + out_proj_b  (batched over B)
        {
            dim3 grid(DD / 128, LL / 128, BB);
            sgemm_bias_kernel<<<grid, 256>>>(patt, pvoT, out_proj_b, pxb,
                                             LL, DD, HH * SS,
                                             (long)LL * HH * SS, (long)DD * HH * SS,
                                             (long)LL * DD);
        }
        // 11. x = rms(x + x_b) ; last round writes d_out
        float* xdst = (it == NB - 1) ? (float*)d_out : px;
        resid_rms_kernel<<<BB * LL, 256>>>(px, pxb, norm_post_w, xdst);
    }
}

// round 4
// speedup vs baseline: 1.9230x; 1.9230x over previous
#include <cuda_runtime.h>
#include <cuda_bf16.h>
#include <cstdint>

// ---------------- problem constants ----------------
#define BB 4
#define LL 2048
#define DD 2048
#define SS 16
#define KK 4
#define NB 2
#define HH 32
#define HD 64
#define EPSF 1e-6f

// ---------------- device scratch (no allocs allowed) ----------------
__device__ float g_x[BB * LL * DD];
__device__ float g_q[BB * LL * DD];
__device__ float g_xb[BB * LL * DD];
__device__ float g_logits[BB * LL * SS];
__device__ float g_ws[BB * SS * DD];
__device__ float g_kv[BB * SS * 2 * DD];
__device__ float g_wxg[BB * SS * KK * DD];
__device__ float g_wgt[BB * SS * KK];
__device__ int   g_idx[BB * SS * KK];

// bf16 hi/lo split operand buffers
__device__ __nv_bfloat16 g_xh[BB * LL * DD],  g_xl[BB * LL * DD];
__device__ __nv_bfloat16 g_wqh[DD * DD],       g_wql[DD * DD];
__device__ __nv_bfloat16 g_wkvh[2 * DD * DD],  g_wkvl[2 * DD * DD];
__device__ __nv_bfloat16 g_wwh[DD * DD],       g_wwl[DD * DD];
__device__ __nv_bfloat16 g_atth[BB * LL * HH * SS], g_attl[BB * LL * HH * SS];
__device__ __nv_bfloat16 g_voTh[BB * DD * HH * SS], g_voTl[BB * DD * HH * SS];
__device__ __nv_bfloat16 g_wsh[BB * SS * DD],  g_wsl[BB * SS * DD];
__device__ __nv_bfloat16 g_xgh[BB * SS * KK * DD], g_xgl[BB * SS * KK * DD];

// ---------------- PTX helpers ----------------
__device__ __forceinline__ void cp16(void* sdst, const void* gsrc) {
    uint32_t d = (uint32_t)__cvta_generic_to_shared(sdst);
    asm volatile("cp.async.cg.shared.global [%0], [%1], 16;\n"
                 :: "r"(d), "l"(gsrc));
}
__device__ __forceinline__ void cp_commit() { asm volatile("cp.async.commit_group;\n"); }
template <int N> __device__ __forceinline__ void cp_wait() {
    asm volatile("cp.async.wait_group %0;\n" :: "n"(N));
}
__device__ __forceinline__ void ldsm4(uint32_t* r, uint32_t saddr) {
    asm volatile("ldmatrix.sync.aligned.m8n8.x4.shared.b16 {%0,%1,%2,%3}, [%4];\n"
                 : "=r"(r[0]), "=r"(r[1]), "=r"(r[2]), "=r"(r[3]) : "r"(saddr));
}
__device__ __forceinline__ void mma16816(float* c, const uint32_t* a, uint32_t b0, uint32_t b1) {
    asm volatile("mma.sync.aligned.m16n8k16.row.col.f32.bf16.bf16.f32 "
                 "{%0,%1,%2,%3}, {%4,%5,%6,%7}, {%8,%9}, {%0,%1,%2,%3};\n"
                 : "+f"(c[0]), "+f"(c[1]), "+f"(c[2]), "+f"(c[3])
                 : "r"(a[0]), "r"(a[1]), "r"(a[2]), "r"(a[3]), "r"(b0), "r"(b1));
}
__device__ __forceinline__ void split1(float v, __nv_bfloat16& h, __nv_bfloat16& l) {
    h = __float2bfloat16(v);
    l = __float2bfloat16(v - __bfloat162float(h));
}

// ---------------- split (weights, once per launch) ----------------
__global__ void split4_kernel(const float* __restrict__ src, __nv_bfloat16* __restrict__ hi,
                              __nv_bfloat16* __restrict__ lo, long n4) {
    long i = (long)blockIdx.x * blockDim.x + threadIdx.x;
    if (i >= n4) return;
    float4 v = ((const float4*)src)[i];
    __nv_bfloat16 h[4], l[4];
    split1(v.x, h[0], l[0]); split1(v.y, h[1], l[1]);
    split1(v.z, h[2], l[2]); split1(v.w, h[3], l[3]);
    __nv_bfloat162 ph0; ph0.x = h[0]; ph0.y = h[1];
    __nv_bfloat162 ph1; ph1.x = h[2]; ph1.y = h[3];
    __nv_bfloat162 pl0; pl0.x = l[0]; pl0.y = l[1];
    __nv_bfloat162 pl1; pl1.x = l[2]; pl1.y = l[3];
    ((__nv_bfloat162*)hi)[2 * i]     = ph0;
    ((__nv_bfloat162*)hi)[2 * i + 1] = ph1;
    ((__nv_bfloat162*)lo)[2 * i]     = pl0;
    ((__nv_bfloat162*)lo)[2 * i + 1] = pl1;
}

// ---------------- init: x <- input (fp32 + hi/lo) ----------------
__global__ void copysplit_kernel(const float* __restrict__ src, float* __restrict__ dst,
                                 __nv_bfloat16* __restrict__ hi, __nv_bfloat16* __restrict__ lo,
                                 long n4) {
    long i = (long)blockIdx.x * blockDim.x + threadIdx.x;
    if (i >= n4) return;
    float4 v = ((const float4*)src)[i];
    ((float4*)dst)[i] = v;
    __nv_bfloat16 h[4], l[4];
    split1(v.x, h[0], l[0]); split1(v.y, h[1], l[1]);
    split1(v.z, h[2], l[2]); split1(v.w, h[3], l[3]);
    __nv_bfloat162 ph0; ph0.x = h[0]; ph0.y = h[1];
    __nv_bfloat162 ph1; ph1.x = h[2]; ph1.y = h[3];
    __nv_bfloat162 pl0; pl0.x = l[0]; pl0.y = l[1];
    __nv_bfloat162 pl1; pl1.x = l[2]; pl1.y = l[3];
    ((__nv_bfloat162*)hi)[2 * i]     = ph0;
    ((__nv_bfloat162*)hi)[2 * i + 1] = ph1;
    ((__nv_bfloat162*)lo)[2 * i]     = pl0;
    ((__nv_bfloat162*)lo)[2 * i + 1] = pl1;
}

__global__ void init_ws_kernel(const float* __restrict__ wsrc, float* __restrict__ ws) {
    int bs = blockIdx.x;
    int s = bs % SS;
    for (int d = threadIdx.x; d < DD; d += blockDim.x)
        ws[(long)bs * DD + d] = wsrc[(long)s * DD + d];
}

// ---------------- bf16x3 emulated-fp32 GEMM ----------------
// C[M,N] = A[M,K] @ W[N,K]^T + bias; 128x128 tile, BK=16, 256 thr, double-buffered cp.async.
// Row indices are clamped for loads (always-valid addresses); M-guard applies at the epilogue.
// Out-of-range rows merely compute garbage that is never written.
__global__ __launch_bounds__(256) void gemm3_kernel(
    const __nv_bfloat16* __restrict__ Ah, const __nv_bfloat16* __restrict__ Al,
    const __nv_bfloat16* __restrict__ Bh, const __nv_bfloat16* __restrict__ Bl,
    const float* __restrict__ bias, float* __restrict__ C,
    int M, int N, int K, long bsA, long bsB, long bsC) {
    Ah += (long)blockIdx.z * bsA; Al += (long)blockIdx.z * bsA;
    Bh += (long)blockIdx.z * bsB; Bl += (long)blockIdx.z * bsB;
    C  += (long)blockIdx.z * bsC;

    __shared__ __align__(16) __nv_bfloat16 sm[2][4][128 * 24];

    const int tid = threadIdx.x;
    const int m0 = blockIdx.y * 128, n0 = blockIdx.x * 128;

    const int lrow = tid >> 1, lhalf = tid & 1;
    int arow = m0 + lrow; if (arow >= M) arow = M - 1;   // clamp: always-valid address
    int brow = n0 + lrow; if (brow >= N) brow = N - 1;
    const long aoff = (long)arow * K + lhalf * 8;
    const long boff = (long)brow * K + lhalf * 8;
    const uint32_t soff = lrow * 24 + lhalf * 8;

    const int NT = K >> 4;

    cp16(&sm[0][0][soff], Ah + aoff);
    cp16(&sm[0][1][soff], Al + aoff);
    cp16(&sm[0][2][soff], Bh + boff);
    cp16(&sm[0][3][soff], Bl + boff);
    cp_commit();

    const int lane = tid & 31, warp = tid >> 5;
    const int wm = (warp & 3) * 32;
    const int wn = (warp >> 2) * 64;

    uint32_t a_row = wm + (lane & 7) + ((lane >> 3) & 1) * 8;
    uint32_t a_k   = (lane >> 4) * 8;
    uint32_t aoffs[2];
    aoffs[0] = ((a_row) * 24 + a_k) * 2;
    aoffs[1] = ((a_row + 16) * 24 + a_k) * 2;
    uint32_t b_row = wn + (lane & 7) + ((lane >> 4) ? 8 : 0);
    uint32_t b_k   = ((lane >> 3) & 1) * 8;
    uint32_t boffs[4];
#pragma unroll
    for (int p = 0; p < 4; p++) boffs[p] = ((b_row + p * 16) * 24 + b_k) * 2;

    const uint32_t smbase = (uint32_t)__cvta_generic_to_shared(&sm[0][0][0]);
    const uint32_t ARR = 128 * 24 * 2;

    float acc[2][8][4];
#pragma unroll
    for (int mt = 0; mt < 2; mt++)
#pragma unroll
        for (int nt = 0; nt < 8; nt++)
#pragma unroll
            for (int j = 0; j < 4; j++) acc[mt][nt][j] = 0.f;

    for (int kt = 0; kt < NT; kt++) {
        const int cur = kt & 1;
        if (kt + 1 < NT) {
            const int nx = cur ^ 1;
            const long kb = (long)(kt + 1) << 4;
            cp16(&sm[nx][0][soff], Ah + aoff + kb);
            cp16(&sm[nx][1][soff], Al + aoff + kb);
            cp16(&sm[nx][2][soff], Bh + boff + kb);
            cp16(&sm[nx][3][soff], Bl + boff + kb);
            cp_commit();
            cp_wait<1>();
        } else {
            cp_wait<0>();
        }
        __syncthreads();

        const uint32_t bAh = smbase + (cur * 4 + 0) * ARR;
        const uint32_t bAl = smbase + (cur * 4 + 1) * ARR;
        const uint32_t bBh = smbase + (cur * 4 + 2) * ARR;
        const uint32_t bBl = smbase + (cur * 4 + 3) * ARR;

        uint32_t ah[2][4], al[2][4], bh[4][4], bl[4][4];
#pragma unroll
        for (int mt = 0; mt < 2; mt++) {
            ldsm4(ah[mt], bAh + aoffs[mt]);
            ldsm4(al[mt], bAl + aoffs[mt]);
        }
#pragma unroll
        for (int p = 0; p < 4; p++) {
            ldsm4(bh[p], bBh + boffs[p]);
            ldsm4(bl[p], bBl + boffs[p]);
        }

#pragma unroll
        for (int mt = 0; mt < 2; mt++)
#pragma unroll
            for (int nt = 0; nt < 8; nt++) {
                uint32_t h0 = bh[nt >> 1][(nt & 1) * 2], h1 = bh[nt >> 1][(nt & 1) * 2 + 1];
                uint32_t l0 = bl[nt >> 1][(nt & 1) * 2], l1 = bl[nt >> 1][(nt & 1) * 2 + 1];
                float* c = acc[mt][nt];
                mma16816(c, ah[mt], h0, h1);
                mma16816(c, ah[mt], l0, l1);
                mma16816(c, al[mt], h0, h1);
            }
        __syncthreads();
    }

#pragma unroll
    for (int mt = 0; mt < 2; mt++) {
        int r0 = m0 + wm + mt * 16 + (lane >> 2);
#pragma unroll
        for (int nt = 0; nt < 8; nt++) {
            int cc = n0 + wn + nt * 8 + (lane & 3) * 2;
            float b0v = bias[cc], b1v = bias[cc + 1];
            float* c = acc[mt][nt];
            if (r0 < M) {
                float2 o; o.x = c[0] + b0v; o.y = c[1] + b1v;
                *(float2*)(C + (long)r0 * N + cc) = o;
            }
            if (r0 + 8 < M) {
                float2 o; o.x = c[2] + b0v; o.y = c[3] + b1v;
                *(float2*)(C + (long)(r0 + 8) * N + cc) = o;
            }
        }
    }
}

// ---------------- compete logits ----------------
__global__ void compete_kernel(const float* __restrict__ x, const float* __restrict__ cw,
                               const float* __restrict__ cb, const float* __restrict__ npw,
                               float* __restrict__ logits) {
    int warp = threadIdx.x >> 5, lane = threadIdx.x & 31;
    int row = blockIdx.x * 8 + warp;
    const float* xr = x + (long)row * DD;
    float ss = 0.f;
    float acc[SS];
#pragma unroll
    for (int s = 0; s < SS; s++) acc[s] = 0.f;
    for (int j = lane; j < DD; j += 32) {
        float xv = xr[j];
        ss += xv * xv;
        float xn = xv * npw[j];
#pragma unroll
        for (int s = 0; s < SS; s++) acc[s] += xn * cw[s * DD + j];
    }
#pragma unroll
    for (int o = 16; o; o >>= 1) ss += __shfl_xor_sync(0xffffffffu, ss, o);
#pragma unroll
    for (int s = 0; s < SS; s++) {
#pragma unroll
        for (int o = 16; o; o >>= 1) acc[s] += __shfl_xor_sync(0xffffffffu, acc[s], o);
    }
    float rinv = rsqrtf(ss * (1.f / DD) + EPSF);
    float myv = 0.f;
#pragma unroll
    for (int s = 0; s < SS; s++) if (lane == s) myv = acc[s];
    if (lane < SS) logits[(long)row * SS + lane] = myv * rinv + cb[lane];
}

// ---------------- top-4 + softmax weights ----------------
__device__ __forceinline__ bool tk_better(float v1, int i1, float v2, int i2) {
    return (v1 > v2) || (v1 == v2 && i1 < i2);
}

__global__ void topk_kernel(const float* __restrict__ logits, int* __restrict__ idxo,
                            float* __restrict__ wgto) {
    int bs = blockIdx.x;
    int b = bs / SS, s = bs % SS;
    float v[KK]; int id[KK];
#pragma unroll
    for (int k = 0; k < KK; k++) { v[k] = -3.4e38f; id[k] = 0x7fffffff; }
    for (int l = threadIdx.x; l < LL; l += 256) {
        float val = logits[((long)b * LL + l) * SS + s];
        if (tk_better(val, l, v[KK - 1], id[KK - 1])) {
            v[KK - 1] = val; id[KK - 1] = l;
#pragma unroll
            for (int j = KK - 1; j > 0; j--) {
                if (tk_better(v[j], id[j], v[j - 1], id[j - 1])) {
                    float tv = v[j]; v[j] = v[j - 1]; v[j - 1] = tv;
                    int ti = id[j]; id[j] = id[j - 1]; id[j - 1] = ti;
                }
            }
        }
    }
    __shared__ float sv[256 * KK];
    __shared__ int   si[256 * KK];
#pragma unroll
    for (int k = 0; k < KK; k++) { sv[threadIdx.x * KK + k] = v[k]; si[threadIdx.x * KK + k] = id[k]; }
    __syncthreads();
    if (threadIdx.x == 0) {
        float bv[KK]; int bi[KK];
#pragma unroll
        for (int k = 0; k < KK; k++) { bv[k] = -3.4e38f; bi[k] = 0x7fffffff; }
        for (int c = 0; c < 256 * KK; c++) {
            float val = sv[c]; int l = si[c];
            if (tk_better(val, l, bv[KK - 1], bi[KK - 1])) {
                bv[KK - 1] = val; bi[KK - 1] = l;
#pragma unroll
                for (int j = KK - 1; j > 0; j--) {
                    if (tk_better(bv[j], bi[j], bv[j - 1], bi[j - 1])) {
                        float tv = bv[j]; bv[j] = bv[j - 1]; bv[j - 1] = tv;
                        int ti = bi[j]; bi[j] = bi[j - 1]; bi[j - 1] = ti;
                    }
                }
            }
        }
        float m = bv[0];
        float e[KK]; float sum = 0.f;
#pragma unroll
        for (int k = 0; k < KK; k++) { e[k] = expf(bv[k] - m); sum += e[k]; }
        float inv = 1.f / sum;
#pragma unroll
        for (int k = 0; k < KK; k++) { wgto[bs * KK + k] = e[k] * inv; idxo[bs * KK + k] = bi[k]; }
    }
}

// ---------------- gather selected rows -> bf16 hi/lo directly ----------------
__global__ void gather_split_kernel(const float* __restrict__ x, const int* __restrict__ idx,
                                    __nv_bfloat16* __restrict__ xgh, __nv_bfloat16* __restrict__ xgl) {
    int r = blockIdx.x;
    int b = r / (SS * KK);
    int l = idx[r];
    const float* src = x + ((long)b * LL + l) * DD;
    for (int d = threadIdx.x; d < DD; d += blockDim.x) {
        __nv_bfloat16 h, lo;
        split1(src[d], h, lo);
        xgh[(long)r * DD + d] = h;
        xgl[(long)r * DD + d] = lo;
    }
}

// ---------------- ws update + rms -> fp32 ws and hi/lo ----------------
__global__ void ws_update_kernel(const float* __restrict__ wxg, const float* __restrict__ wgt,
                                 const float* __restrict__ npw, float* __restrict__ ws,
                                 __nv_bfloat16* __restrict__ wsh, __nv_bfloat16* __restrict__ wsl) {
    int bs = blockIdx.x;
    __shared__ float t[DD];
    __shared__ float red[256];
    float w0 = wgt[bs * KK + 0], w1 = wgt[bs * KK + 1];
    float w2 = wgt[bs * KK + 2], w3 = wgt[bs * KK + 3];
    const float* r0 = wxg + (long)(bs * KK + 0) * DD;
    const float* r1 = wxg + (long)(bs * KK + 1) * DD;
    const float* r2 = wxg + (long)(bs * KK + 2) * DD;
    const float* r3 = wxg + (long)(bs * KK + 3) * DD;
    float ssp = 0.f;
    for (int d = threadIdx.x; d < DD; d += 256) {
        float v = ws[(long)bs * DD + d] + w0 * r0[d] + w1 * r1[d] + w2 * r2[d] + w3 * r3[d];
        t[d] = v; ssp += v * v;
    }
    red[threadIdx.x] = ssp; __syncthreads();
    for (int st = 128; st; st >>= 1) {
        if (threadIdx.x < st) red[threadIdx.x] += red[threadIdx.x + st];
        __syncthreads();
    }
    float rinv = rsqrtf(red[0] * (1.f / DD) + EPSF);
    for (int d = threadIdx.x; d < DD; d += 256) {
        float v = t[d] * rinv * npw[d];
        ws[(long)bs * DD + d] = v;
        __nv_bfloat16 h, lo;
        split1(v, h, lo);
        wsh[(long)bs * DD + d] = h;
        wsl[(long)bs * DD + d] = lo;
    }
}

// ---------------- fold vv with out_proj -> voT hi/lo ----------------
__global__ __launch_bounds__(128) void vo_kernel(const float* __restrict__ kv,
                                                 const float* __restrict__ wout,
                                                 __nv_bfloat16* __restrict__ voTh,
                                                 __nv_bfloat16* __restrict__ voTl) {
    int b = blockIdx.y / HH, h = blockIdx.y % HH;
    int d0 = blockIdx.x * 128;
    __shared__ float vs[SS][HD];
    __shared__ float wsm[128][HD + 1];
    for (int e = threadIdx.x; e < SS * HD; e += 128) {
        int s = e >> 6, i = e & 63;
        vs[s][i] = kv[((long)b * SS + s) * (2 * DD) + DD + h * HD + i];
    }
    for (int e = threadIdx.x; e < 128 * HD; e += 128) {
        int r = e >> 6, i = e & 63;
        wsm[r][i] = wout[(long)(d0 + r) * DD + h * HD + i];
    }
    __syncthreads();
    int d = threadIdx.x;
    float acc[SS];
#pragma unroll
    for (int s = 0; s < SS; s++) acc[s] = 0.f;
#pragma unroll
    for (int i = 0; i < HD; i++) {
        float w = wsm[d][i];
#pragma unroll
        for (int s = 0; s < SS; s++) acc[s] += w * vs[s][i];
    }
    long base = ((long)b * DD + d0 + d) * (HH * SS) + h * SS;
#pragma unroll
    for (int s = 0; s < SS; s++) {
        __nv_bfloat16 hh, ll;
        split1(acc[s], hh, ll);
        voTh[base + s] = hh;
        voTl[base + s] = ll;
    }
}

// ---------------- attention scores + softmax -> att hi/lo ----------------
__global__ __launch_bounds__(256) void att_kernel(const float* __restrict__ q,
                                                  const float* __restrict__ kv,
                                                  __nv_bfloat16* __restrict__ atth,
                                                  __nv_bfloat16* __restrict__ attl) {
    int b = blockIdx.y / HH, h = blockIdx.y % HH;
    int l0 = blockIdx.x * 64;
    __shared__ float ks[SS][HD];
    __shared__ float qs[64][HD + 1];
    __shared__ float sc[64][SS + 1];
    for (int e = threadIdx.x; e < SS * HD; e += 256) {
        int s = e >> 6, i = e & 63;
        ks[s][i] = kv[((long)b * SS + s) * (2 * DD) + h * HD + i];
    }
    for (int e = threadIdx.x; e < 64 * HD; e += 256) {
        int r = e >> 6, i = e & 63;
        qs[r][i] = q[((long)b * LL + l0 + r) * DD + h * HD + i];
    }
    __syncthreads();
    int r = threadIdx.x & 63, sg = threadIdx.x >> 6;
#pragma unroll
    for (int j = 0; j < 4; j++) {
        int s = sg * 4 + j;
        float a = 0.f;
#pragma unroll
        for (int i = 0; i < HD; i++) a += qs[r][i] * ks[s][i];
        sc[r][s] = a * 0.125f;
    }
    __syncthreads();
    if (threadIdx.x < 64) {
        int rr = threadIdx.x;
        float m = sc[rr][0];
#pragma unroll
        for (int s = 1; s < SS; s++) m = fmaxf(m, sc[rr][s]);
        float e[SS]; float sum = 0.f;
#pragma unroll
        for (int s = 0; s < SS; s++) { e[s] = expf(sc[rr][s] - m); sum += e[s]; }
        float inv = 1.f / sum;
        long base = ((long)b * LL + l0 + rr) * (HH * SS) + h * SS;
#pragma unroll
        for (int s = 0; s < SS; s++) {
            __nv_bfloat16 hh, ll;
            split1(e[s] * inv, hh, ll);
            atth[base + s] = hh;
            attl[base + s] = ll;
        }
    }
}

// ---------------- x = rms(x + xb) -> fp32 out (+ hi/lo split for next round) ----------------
__global__ void resid_rms_kernel(const float* __restrict__ xin, const float* __restrict__ xb,
                                 const float* __restrict__ npw, float* __restrict__ xout,
                                 __nv_bfloat16* __restrict__ xh, __nv_bfloat16* __restrict__ xl) {
    long row = blockIdx.x;
    __shared__ float t[DD];
    __shared__ float red[256];
    const float* a = xin + row * DD;
    const float* c = xb + row * DD;
    float ssp = 0.f;
    for (int d = threadIdx.x; d < DD; d += 256) {
        float v = a[d] + c[d];
        t[d] = v; ssp += v * v;
    }
    red[threadIdx.x] = ssp; __syncthreads();
    for (int st = 128; st; st >>= 1) {
        if (threadIdx.x < st) red[threadIdx.x] += red[threadIdx.x + st];
        __syncthreads();
    }
    float rinv = rsqrtf(red[0] * (1.f / DD) + EPSF);
    for (int d = threadIdx.x; d < DD; d += 256) {
        float v = t[d] * rinv * npw[d];
        xout[row * DD + d] = v;
        __nv_bfloat16 h, l;
        split1(v, h, l);
        xh[row * DD + d] = h;
        xl[row * DD + d] = l;
    }
}

// ---------------- host launch ----------------
static inline void run_split(const float* src, __nv_bfloat16* hi, __nv_bfloat16* lo, long n) {
    long n4 = n >> 2;
    split4_kernel<<<(int)((n4 + 255) / 256), 256>>>(src, hi, lo, n4);
}

extern "C" void kernel_launch(void* const* d_in, const int* in_sizes, int n_in,
                              void* d_out, int out_size) {
    const float* x_in       = (const float*)d_in[0];
    const float* workspace  = (const float*)d_in[1];
    const float* compete_w  = (const float*)d_in[2];
    const float* compete_b  = (const float*)d_in[3];
    const float* write_w    = (const float*)d_in[4];
    const float* write_b    = (const float*)d_in[5];
    const float* in_proj_w  = (const float*)d_in[6];
    const float* in_proj_b  = (const float*)d_in[7];
    const float* out_proj_w = (const float*)d_in[8];
    const float* out_proj_b = (const float*)d_in[9];
    const float* norm_pre_w  = (const float*)d_in[12];
    const float* norm_post_w = (const float*)d_in[13];

    void *p;
    float *px, *pq, *pxb, *plog, *pws, *pkv, *pwxg, *pwgt;
    int *pidx;
    __nv_bfloat16 *pxh, *pxl, *pwqh, *pwql, *pwkvh, *pwkvl, *pwwh, *pwwl;
    __nv_bfloat16 *patth, *pattl, *pvoTh, *pvoTl, *pwsh, *pwsl, *pxgh, *pxgl;
    cudaGetSymbolAddress(&p, g_x);    px   = (float*)p;
    cudaGetSymbolAddress(&p, g_q);    pq   = (float*)p;
    cudaGetSymbolAddress(&p, g_xb);   pxb  = (float*)p;
    cudaGetSymbolAddress(&p, g_logits); plog = (float*)p;
    cudaGetSymbolAddress(&p, g_ws);   pws  = (float*)p;
    cudaGetSymbolAddress(&p, g_kv);   pkv  = (float*)p;
    cudaGetSymbolAddress(&p, g_wxg);  pwxg = (float*)p;
    cudaGetSymbolAddress(&p, g_wgt);  pwgt = (float*)p;
    cudaGetSymbolAddress(&p, g_idx);  pidx = (int*)p;
    cudaGetSymbolAddress(&p, g_xh);   pxh  = (__nv_bfloat16*)p;
    cudaGetSymbolAddress(&p, g_xl);   pxl  = (__nv_bfloat16*)p;
    cudaGetSymbolAddress(&p, g_wqh);  pwqh = (__nv_bfloat16*)p;
    cudaGetSymbolAddress(&p, g_wql);  pwql = (__nv_bfloat16*)p;
    cudaGetSymbolAddress(&p, g_wkvh); pwkvh = (__nv_bfloat16*)p;
    cudaGetSymbolAddress(&p, g_wkvl); pwkvl = (__nv_bfloat16*)p;
    cudaGetSymbolAddress(&p, g_wwh);  pwwh = (__nv_bfloat16*)p;
    cudaGetSymbolAddress(&p, g_wwl);  pwwl = (__nv_bfloat16*)p;
    cudaGetSymbolAddress(&p, g_atth); patth = (__nv_bfloat16*)p;
    cudaGetSymbolAddress(&p, g_attl); pattl = (__nv_bfloat16*)p;
    cudaGetSymbolAddress(&p, g_voTh); pvoTh = (__nv_bfloat16*)p;
    cudaGetSymbolAddress(&p, g_voTl); pvoTl = (__nv_bfloat16*)p;
    cudaGetSymbolAddress(&p, g_wsh);  pwsh = (__nv_bfloat16*)p;
    cudaGetSymbolAddress(&p, g_wsl);  pwsl = (__nv_bfloat16*)p;
    cudaGetSymbolAddress(&p, g_xgh);  pxgh = (__nv_bfloat16*)p;
    cudaGetSymbolAddress(&p, g_xgl);  pxgl = (__nv_bfloat16*)p;

    // init: x <- input (fp32 + hi/lo), ws <- broadcast(workspace)
    {
        long n4 = (long)BB * LL * DD / 4;
        copysplit_kernel<<<(int)((n4 + 255) / 256), 256>>>(x_in, px, pxh, pxl, n4);
        init_ws_kernel<<<BB * SS, 256>>>(workspace, pws);
    }
    // weight splits (once per launch)
    run_split(in_proj_w, pwqh, pwql, (long)DD * DD);
    run_split(in_proj_w + (long)DD * DD, pwkvh, pwkvl, (long)2 * DD * DD);
    run_split(write_w, pwwh, pwwl, (long)DD * DD);

    for (int it = 0; it < NB; it++) {
        // 1. compete logits (fp32)
        compete_kernel<<<BB * LL / 8, 256>>>(px, compete_w, compete_b, norm_pre_w, plog);
        // 2. top-k + softmax weights
        topk_kernel<<<BB * SS, 256>>>(plog, pidx, pwgt);
        // 3. gather + split fused
        gather_split_kernel<<<BB * SS * KK, 256>>>(px, pidx, pxgh, pxgl);
        // 4. write projection (256 x 2048 x 2048)
        {
            dim3 grid(DD / 128, 2, 1);
            gemm3_kernel<<<grid, 256>>>(pxgh, pxgl, pwwh, pwwl, write_b, pwxg,
                                        BB * SS * KK, DD, DD, 0, 0, 0);
        }
        // 5. workspace update + rms (+hi/lo)
        ws_update_kernel<<<BB * SS, 256>>>(pwxg, pwgt, norm_post_w, pws, pwsh, pwsl);
        // 6. kk|vv projection (64 x 4096 x 2048)
        {
            dim3 grid((2 * DD) / 128, 1, 1);
            gemm3_kernel<<<grid, 256>>>(pwsh, pwsl, pwkvh, pwkvl, in_proj_b + DD, pkv,
                                        BB * SS, 2 * DD, DD, 0, 0, 0);
        }
        // 7. q projection (8192 x 2048 x 2048) — the big one
        {
            dim3 grid(DD / 128, BB * LL / 128, 1);
            gemm3_kernel<<<grid, 256>>>(pxh, pxl, pwqh, pwql, in_proj_b, pq,
                                        BB * LL, DD, DD, 0, 0, 0);
        }
        // 8. fold vv with out_proj -> voT hi/lo
        {
            dim3 grid(DD / 128, BB * HH, 1);
            vo_kernel<<<grid, 128>>>(pkv, out_proj_w, pvoTh, pvoTl);
        }
        // 9. attention scores + softmax -> att hi/lo
        {
            dim3 grid(LL / 64, BB * HH, 1);
            att_kernel<<<grid, 256>>>(pq, pkv, patth, pattl);
        }
        // 10. x_b = att @ voT^T + out_proj_b (batched over B; 2048 x 2048 x 512)
        {
            dim3 grid(DD / 128, LL / 128, BB);
            gemm3_kernel<<<grid, 256>>>(patth, pattl, pvoTh, pvoTl, out_proj_b, pxb,
                                        LL, DD, HH * SS,
                                        (long)LL * HH * SS, (long)DD * HH * SS,
                                        (long)LL * DD);
        }
        // 11. x = rms(x + x_b) (+hi/lo for next round); last round writes d_out
        float* xdst = (it == NB - 1) ? (float*)d_out : px;
        resid_rms_kernel<<<BB * LL, 256>>>(px, pxb, norm_post_w, xdst, pxh, pxl);
    }
}